// round 3
// baseline (speedup 1.0000x reference)
#include <cuda_runtime.h>

// Problem constants
#define BB 2
#define BN 4096
#define PARTS 8
#define CPART (BN / PARTS)       // 512 columns per partition
#define RPB 256                  // rows per block / threads per block
#define ROWTILES (BN / RPB)      // 16
#define LOG2E 1.4426950408889634f
#define LN2 0.6931471805599453f

// Scratch (allocation-free): duals, squared half-norms, per-partition LSE partials
__device__ float g_x2[BB * BN];
__device__ float g_y2[BB * BN];
__device__ float g_ax[BB * BN];
__device__ float g_by[BB * BN];
__device__ float g_bx[BB * BN];
__device__ float g_ay[BB * BN];
__device__ float g_pm[4 * BB * PARTS * BN];
__device__ float g_ps[4 * BB * PARTS * BN];

__device__ __forceinline__ float ex2f(float x) {
    float r;
    asm("ex2.approx.f32 %0, %1;" : "=f"(r) : "f"(x));
    return r;
}
__device__ __forceinline__ float lg2f(float x) {
    float r;
    asm("lg2.approx.f32 %0, %1;" : "=f"(r) : "f"(x));
    return r;
}

// Precompute 0.5*||p||^2 for both point sets
__global__ void sqnorm_kernel(const float* __restrict__ X, const float* __restrict__ Y) {
    int i = blockIdx.x * blockDim.x + threadIdx.x;
    if (i < BB * BN) {
        float a = X[3 * i], b = X[3 * i + 1], c = X[3 * i + 2];
        g_x2[i] = 0.5f * (a * a + b * b + c * c);
        a = Y[3 * i]; b = Y[3 * i + 1]; c = Y[3 * i + 2];
        g_y2[i] = 0.5f * (a * a + b * b + c * c);
    }
}

// One stage: 4 softmins, each row x col-partition computes partial (max, sum) in log2 domain.
//
// softmin(eps, C, h)_i = -eps * ln( sum_j exp(h_j - C_ij/eps) )
// with C_ij = 0.5|x_i|^2 + 0.5|y_j|^2 - x_i.y_j.
// Work in base-2:
//   g_j  = -12 + (dual_j*dualScale - 0.5|y_j|^2) * (log2e/eps)      [col constant; -12 = log2(1/4096)]
//   v_ij = g_j + (x_i * log2e/eps) . y_j                             [3 FFMA]
//   row constant r_i = -0.5|x_i|^2 * log2e/eps  added in merge.
// Tasks: t0: C_xx h=a_x -> a_x | t1: C_yy h=b_y -> b_y | t2: C_xy h=a_y -> b_x | t3: C_yx h=b_x -> a_y
__global__ __launch_bounds__(RPB) void softmin_kernel(const float* __restrict__ X,
                                                      const float* __restrict__ Y,
                                                      float eps, float dualScale) {
    __shared__ float4 shY[CPART];

    int bi = blockIdx.x;
    int part    = bi & (PARTS - 1);
    int rowTile = (bi >> 3) & (ROWTILES - 1);
    int b       = (bi >> 7) & (BB - 1);
    int task    = bi >> 8;

    const float* rowP = (task == 0 || task == 2) ? X : Y;
    const float* colP = (task == 0 || task == 3) ? X : Y;
    const float* colQ = (task == 0 || task == 3) ? g_x2 : g_y2;
    const float* colD = (task == 0) ? g_ax : (task == 1) ? g_by : (task == 2) ? g_ay : g_bx;

    const float sLe = LOG2E / eps;
    int tid = threadIdx.x;

    // Load column tile: coords + folded column constant g_j
    for (int jj = tid; jj < CPART; jj += RPB) {
        int j  = part * CPART + jj;
        int gj = b * BN + j;
        float y0 = colP[3 * gj], y1 = colP[3 * gj + 1], y2 = colP[3 * gj + 2];
        float g  = -12.0f + (colD[gj] * dualScale - colQ[gj]) * sLe;
        shY[jj] = make_float4(y0, y1, y2, g);
    }
    __syncthreads();

    int r  = rowTile * RPB + tid;
    int gr = b * BN + r;
    float xs0 = rowP[3 * gr] * sLe;
    float xs1 = rowP[3 * gr + 1] * sLe;
    float xs2 = rowP[3 * gr + 2] * sLe;

    float m = -3.0e38f, s0 = 0.f, s1 = 0.f;
    for (int jj = 0; jj < CPART; jj += 8) {
        float v[8];
#pragma unroll
        for (int k = 0; k < 8; k++) {
            float4 c = shY[jj + k];
            v[k] = fmaf(xs0, c.x, fmaf(xs1, c.y, fmaf(xs2, c.z, c.w)));
        }
        float cm = fmaxf(fmaxf(fmaxf(v[0], v[1]), fmaxf(v[2], v[3])),
                         fmaxf(fmaxf(v[4], v[5]), fmaxf(v[6], v[7])));
        float mn = fmaxf(m, cm);
        float sc = ex2f(m - mn);
        s0 *= sc;
        s1 *= sc;
#pragma unroll
        for (int k = 0; k < 8; k += 2) {
            s0 += ex2f(v[k] - mn);
            s1 += ex2f(v[k + 1] - mn);
        }
        m = mn;
    }
    int pidx = ((task * BB + b) * PARTS + part) * BN + r;
    g_pm[pidx] = m;
    g_ps[pidx] = s0 + s1;
}

// Combine partition partials -> softmin value; optionally average with old dual (in place).
__global__ void merge_kernel(float eps, int avg) {
    int idx = blockIdx.x * blockDim.x + threadIdx.x;
    if (idx >= 4 * BB * BN) return;
    int task = idx / (BB * BN);
    int rem  = idx - task * (BB * BN);       // b*BN + r
    int b    = rem / BN;
    int r    = rem - b * BN;

    const float* rowQ = (task == 0 || task == 2) ? g_x2 : g_y2;
    float* outA = (task == 0) ? g_ax : (task == 1) ? g_by : (task == 2) ? g_bx : g_ay;

    int base = (task * BB + b) * (PARTS * BN) + r;
    float M = -3.0e38f;
#pragma unroll
    for (int p = 0; p < PARTS; p++) M = fmaxf(M, g_pm[base + p * BN]);
    float s = 0.f;
#pragma unroll
    for (int p = 0; p < PARTS; p++)
        s = fmaf(g_ps[base + p * BN], ex2f(g_pm[base + p * BN] - M), s);

    float sLe = LOG2E / eps;
    float ri  = -rowQ[rem] * sLe;
    float val = -eps * LN2 * (ri + M + lg2f(s));
    if (avg) val = 0.5f * (outA[rem] + val);
    outA[rem] = val;
}

// F = sum_b [ (1/N) sum_i (b_x - a_x) + (1/M) sum_j (a_y - b_y) ]
__global__ void reduce_kernel(float* __restrict__ out) {
    __shared__ float sh[32];
    int tid = threadIdx.x;
    float acc = 0.f;
    for (int i = tid; i < BB * BN; i += blockDim.x)
        acc += (g_bx[i] - g_ax[i]) + (g_ay[i] - g_by[i]);
    acc *= (1.0f / BN);
#pragma unroll
    for (int o = 16; o; o >>= 1) acc += __shfl_down_sync(0xFFFFFFFFu, acc, o);
    if ((tid & 31) == 0) sh[tid >> 5] = acc;
    __syncthreads();
    if (tid < 32) {
        float v = (tid < (int)(blockDim.x >> 5)) ? sh[tid] : 0.f;
#pragma unroll
        for (int o = 16; o; o >>= 1) v += __shfl_down_sync(0xFFFFFFFFu, v, o);
        if (tid == 0) out[0] = v;
    }
}

extern "C" void kernel_launch(void* const* d_in, const int* in_sizes, int n_in,
                              void* d_out, int out_size) {
    const float* X = (const float*)d_in[0];   // true_data
    const float* Y = (const float*)d_in[1];   // particles
    float* out = (float*)d_out;

    sqnorm_kernel<<<(BB * BN + 255) / 256, 256>>>(X, Y);

    // geomloss eps schedule: [16] + [16,4,1,0.25,0.0625,0.015625,0.00390625] + [0.0025]
    const float epsList[9] = {16.f, 16.f, 4.f, 1.f, 0.25f, 0.0625f,
                              0.015625f, 0.00390625f, 0.0025f};

    const int gridSoft = 4 * BB * ROWTILES * PARTS;   // 1024 blocks
    const int gridMerge = (4 * BB * BN) / 256;        // 128 blocks

    // init (dual term off, assignment)
    softmin_kernel<<<gridSoft, RPB>>>(X, Y, 16.f, 0.f);
    merge_kernel<<<gridMerge, 256>>>(16.f, 0);

    // eps-scaling loop (symmetrized, averaged updates)
    for (int e = 0; e < 9; e++) {
        softmin_kernel<<<gridSoft, RPB>>>(X, Y, epsList[e], 1.f);
        merge_kernel<<<gridMerge, 256>>>(epsList[e], 1);
    }

    // final extrapolation at blur^2 (assignment, no averaging)
    softmin_kernel<<<gridSoft, RPB>>>(X, Y, 0.0025f, 1.f);
    merge_kernel<<<gridMerge, 256>>>(0.0025f, 0);

    reduce_kernel<<<1, 256>>>(out);
}